// round 2
// baseline (speedup 1.0000x reference)
#include <cuda_runtime.h>
#include <math.h>

#define NH 8
#define SEQ 32
#define DK 8
#define DM 64
#define PI_F 3.14159265358979323846f
#define W_MUL 0.6324555320336759f  // sqrt(2)/sqrt(5)

// scratch
static __device__ float  g_phi [NH * SEQ * SEQ];   // [h][i][j]
static __device__ float2 g_phiv[NH * SEQ * DK];    // [h][s][e]
static __device__ float  g_z   [SEQ * NH * DK];    // [s][h*8+a]

__device__ __forceinline__ float2 cmul(float2 a, float2 b) {
    return make_float2(fmaf(a.x, b.x, -a.y * b.y), fmaf(a.x, b.y, a.y * b.x));
}
// a * conj(b)
__device__ __forceinline__ float2 cmulc(float2 a, float2 b) {
    return make_float2(fmaf(a.x, b.x, a.y * b.y), fmaf(a.y, b.x, -a.x * b.y));
}
__device__ __forceinline__ float2 cadd(float2 a, float2 b) {
    return make_float2(a.x + b.x, a.y + b.y);
}

// CNOT-ring basis permutation f(x)
__device__ __forceinline__ int permf(int x) {
#pragma unroll
    for (int t = 0; t < 6; t++) {
        int cb = 5 - t;
        int tb = 5 - ((t + 1) % 6);
        if ((x >> cb) & 1) x ^= (1 << tb);
    }
    return x;
}

// sum within groups of 8 lanes (butterfly over lane bits 0..2)
__device__ __forceinline__ float2 bfly_sum8(float2 v) {
#pragma unroll
    for (int d = 1; d < 8; d <<= 1) {
        v.x += __shfl_xor_sync(0xffffffffu, v.x, d);
        v.y += __shfl_xor_sync(0xffffffffu, v.y, d);
    }
    return v;
}

// ---------------- Kernel 1: per-head prep ----------------
// computes psi, per-qubit unitaries, q/k diagonals, phi matrix, phiv
__global__ void __launch_bounds__(128)
qprep(const float* __restrict__ x,     // (32,64)
      const float* __restrict__ pqc,   // (8,3,9)
      const float* __restrict__ W1,    // (8,64)
      const float* __restrict__ b1)    // (8,)
{
    const int h = blockIdx.x;
    const int t = threadIdx.x;   // 0..127

    __shared__ float  s_xq [SEQ][DK];
    __shared__ float  s_psi[SEQ][DK];
    __shared__ float2 s_u[3][3][4];
    __shared__ float  s_qd[SEQ][DK];
    __shared__ float  s_kd[SEQ][DK];
    __shared__ float  s_ms[64];

    if (t < 64) {
        int y = permf(t);
        s_ms[t] = (__popc(y) & 1) ? -1.0f : 1.0f;
    }

    // xq = x @ W1^T + b1
#pragma unroll
    for (int k = 0; k < 2; k++) {
        int idx = t + 128 * k;           // 0..255
        int s = idx >> 3, cc = idx & 7;
        float acc = b1[cc];
        const float* xr = x + s * DM;
        const float* wr = W1 + cc * DM;
#pragma unroll 8
        for (int d = 0; d < DM; d++) acc = fmaf(xr[d], wr[d], acc);
        s_xq[s][cc] = acc;
    }
    __syncthreads();
#pragma unroll
    for (int k = 0; k < 2; k++) {
        int idx = t + 128 * k;
        int s = idx >> 3, cc = idx & 7;
        float n = 0.f;
#pragma unroll
        for (int e = 0; e < DK; e++) n = fmaf(s_xq[s][e], s_xq[s][e], n);
        s_psi[s][cc] = s_xq[s][cc] * rsqrtf(n);
    }

    // per-qubit 2x2 unitaries
    if (t < 9) {
        int g = t / 3, q = t % 3;
        const float* ap = pqc + h * 27 + g * 9 + q * 3;
        float a0 = ap[0] * W_MUL, a1 = ap[1] * W_MUL, a2 = ap[2] * W_MUL;
        float sx, cx, sy, cy, sz, cz;
        sincosf(0.5f * a0, &sx, &cx);
        sincosf(0.5f * a1, &sy, &cy);
        sincosf(0.5f * a2, &sz, &cz);
        float2 m00 = make_float2(cy * cx,   sy * sx);
        float2 m01 = make_float2(-sy * cx, -cy * sx);
        float2 m10 = make_float2(sy * cx,  -cy * sx);
        float2 m11 = make_float2(cy * cx,  -sy * sx);
        float2 e0 = make_float2(cz, -sz);
        float2 e1 = make_float2(cz,  sz);
        s_u[g][q][0] = cmul(e0, m00);
        s_u[g][q][1] = cmul(e0, m01);
        s_u[g][q][2] = cmul(e1, m10);
        s_u[g][q][3] = cmul(e1, m11);
    }
    __syncthreads();

    // apply 3-qubit unitary per (g, s)
    if (t < 96) {
        int g = t >> 5, s = t & 31;
        float2 v[8];
#pragma unroll
        for (int e = 0; e < 8; e++) v[e] = make_float2(s_psi[s][e], 0.f);
#pragma unroll
        for (int q = 0; q < 3; q++) {
            int p = 2 - q;
            float2 u0 = s_u[g][q][0], u1 = s_u[g][q][1];
            float2 u2 = s_u[g][q][2], u3 = s_u[g][q][3];
#pragma unroll
            for (int k = 0; k < 8; k++) {
                if ((k >> p) & 1) continue;
                int k1 = k | (1 << p);
                float2 v0 = v[k], v1 = v[k1];
                v[k]  = cadd(cmul(u0, v0), cmul(u1, v1));
                v[k1] = cadd(cmul(u2, v0), cmul(u3, v1));
            }
        }
        if (g == 0) {
#pragma unroll
            for (int e = 0; e < 8; e++)
                s_qd[s][e] = fmaf(v[e].x, v[e].x, v[e].y * v[e].y);
        } else if (g == 1) {
#pragma unroll
            for (int e = 0; e < 8; e++)
                s_kd[s][e] = fmaf(v[e].x, v[e].x, v[e].y * v[e].y);
        } else {
#pragma unroll
            for (int e = 0; e < 8; e++) g_phiv[h * 256 + s * 8 + e] = v[e];
        }
    }
    __syncthreads();

    // phi[i][j] = pi * sum_{c,d} ms[8c+d] qd[i][c] kd[j][d]
#pragma unroll
    for (int k = 0; k < 8; k++) {
        int idx = t + 128 * k;           // 0..1023
        int i = idx >> 5, j = idx & 31;
        float acc = 0.f;
#pragma unroll
        for (int cc = 0; cc < 8; cc++) {
            float qv = s_qd[i][cc];
#pragma unroll
            for (int d = 0; d < 8; d++)
                acc = fmaf(s_ms[cc * 8 + d] * qv, s_kd[j][d], acc);
        }
        g_phi[h * 1024 + i * 32 + j] = acc * PI_F;
    }
}

// ---------------- Kernel 2: warp-synchronous scan ----------------
__global__ void __launch_bounds__(32)
qscan()
{
    const int h = blockIdx.x >> 5;
    const int i = blockIdx.x & 31;
    const int l = threadIdx.x;       // 0..31
    const int a0 = l >> 3;           // 0..3 (elem1 row = a0+4)
    const int c  = l & 7;

    __shared__ int    s_finv[64];
    __shared__ float2 s_uj[SEQ][4];
    __shared__ float2 s_phiv[SEQ][DK];
    __shared__ float2 s_chi[8];
    __shared__ float2 s_rho[2][64];

    // finv table
    {
        int y0 = permf(l);      s_finv[y0] = l;
        int y1 = permf(l + 32); s_finv[y1] = l + 32;
    }

    // copy phiv for this head
    {
        const float2* gp = g_phiv + h * 256;
        float2* dst = &s_phiv[0][0];
#pragma unroll
        for (int k = 0; k < 8; k++) dst[l + 32 * k] = gp[l + 32 * k];
    }

    // lane j builds u(phi[i][j])
    {
        float ph = g_phi[h * 1024 + i * 32 + l];
        float s4, c4, sh, ch;
        sincosf(0.25f * ph, &s4, &c4);
        sincosf(0.50f * ph, &sh, &ch);
        float cc2 = c4 * c4, ss2 = s4 * s4, cs2 = c4 * s4;
        float2 e0 = make_float2(ch, -sh);
        float2 e1 = make_float2(ch,  sh);
        s_uj[l][0] = cmul(e0, make_float2(cc2,  ss2));
        s_uj[l][1] = cmul(e0, make_float2(-cs2, -cs2));
        s_uj[l][2] = cmul(e1, make_float2(cs2,  -cs2));
        s_uj[l][3] = cmul(e1, make_float2(cc2,  -ss2));
    }
    __syncwarp();

    // per-lane gather tables (runtime values, statically indexed)
    int ro0[8], ro1[8], co0[8], co1[8], coc[8];
#pragma unroll
    for (int b = 0; b < 8; b++) {
        int i0 = s_finv[a0 * 8 + b];
        int i1 = s_finv[(a0 + 4) * 8 + b];
        int ic = s_finv[c * 8 + b];
        ro0[b] = (i0 >> 3) * 8 + (ic >> 3);
        ro1[b] = (i1 >> 3) * 8 + (ic >> 3);
        co0[b] = i0 & 7;
        co1[b] = i1 & 7;
        coc[b] = ic & 7;
    }

    // lane-static u-factor indices: u[k], k = (rowbit<<1)|colbit
    const int kf2a = (c >> 2) & 1;            // elem0: row bit2 = 0
    const int kf2b = 2 | ((c >> 2) & 1);      // elem1: row bit2 = 1
    const int kf1  = (((a0 >> 1) & 1) << 1) | ((c >> 1) & 1);
    const int kf0  = ((a0 & 1) << 1) | (c & 1);

    float2 acc0 = make_float2(0.f, 0.f), acc1 = make_float2(0.f, 0.f);
    int cur = 0;

    for (int j = 0; j < SEQ; j++) {
        const float2* uj = s_uj[j];
        float2 f20 = uj[kf2a], f21 = uj[kf2b];
        float2 f1  = uj[kf1],  f0  = uj[kf0];
        float2 pv  = s_phiv[j][c];

        float2 g  = cmul(f1, f0);
        float2 gp = cmul(g, pv);
        float2 t0 = cmul(f20, gp);
        float2 t1 = cmul(f21, gp);

        t0 = bfly_sum8(t0);   // chi[a0]
        t1 = bfly_sum8(t1);   // chi[a0+4]

        if ((l & 7) == 0) {
            s_chi[a0]     = t0;
            s_chi[a0 + 4] = t1;
        }
        __syncwarp();

        if (j == 0) {
            acc0 = cmulc(s_chi[a0],     s_chi[c]);
            acc1 = cmulc(s_chi[a0 + 4], s_chi[c]);
        } else {
            const float2* rp = s_rho[cur];
            acc0 = make_float2(0.f, 0.f);
            acc1 = make_float2(0.f, 0.f);
#pragma unroll
            for (int b = 0; b < 8; b++) {
                float2 cq = s_chi[coc[b]];
                float2 c0 = s_chi[co0[b]];
                float2 c1 = s_chi[co1[b]];
                float2 w0 = cmulc(c0, cq);
                float2 w1 = cmulc(c1, cq);
                float2 r0 = rp[ro0[b]];
                float2 r1 = rp[ro1[b]];
                acc0 = cadd(acc0, cmul(r0, w0));
                acc1 = cadd(acc1, cmul(r1, w1));
            }
        }
        // write new rho into the other buffer; one syncwarp covers
        // (a) everyone done reading s_chi + old rho, (b) new rho visible
        s_rho[cur ^ 1][l]      = acc0;
        s_rho[cur ^ 1][l + 32] = acc1;
        cur ^= 1;
        __syncwarp();
    }

    if (l < 8) {
        float2 v = s_rho[cur][l * 9];       // diag element (l,l)
        g_z[i * (NH * DK) + h * DK + l] = v.x;
    }
}

// ---------------- Kernel 3: output projection ----------------
__global__ void __launch_bounds__(64)
qout(const float* __restrict__ W2,   // (64,64)
     const float* __restrict__ b2,   // (64,)
     float* __restrict__ out)        // (1,32,64)
{
    const int s = blockIdx.x;   // 0..31
    const int t = threadIdx.x;  // 0..63

    __shared__ float sW[DM * 65];   // padded to kill bank conflicts
    __shared__ float sz[DM];

    sz[t] = g_z[s * DM + t];
#pragma unroll
    for (int k = 0; k < 64; k++) {
        int idx = t + 64 * k;           // coalesced linear load of W2
        sW[(idx >> 6) * 65 + (idx & 63)] = W2[idx];
    }
    __syncthreads();

    float acc = b2[t];
#pragma unroll
    for (int e = 0; e < DM; e++)
        acc = fmaf(sz[e], sW[t * 65 + e], acc);
    out[s * DM + t] = acc;
}

extern "C" void kernel_launch(void* const* d_in, const int* in_sizes, int n_in,
                              void* d_out, int out_size) {
    const float* x    = (const float*)d_in[0];
    const float* pqc  = (const float*)d_in[1];
    const float* W1   = (const float*)d_in[2];
    const float* b1   = (const float*)d_in[3];
    const float* W2   = (const float*)d_in[4];
    const float* b2   = (const float*)d_in[5];
    float* out = (float*)d_out;

    qprep<<<NH, 128>>>(x, pqc, W1, b1);
    qscan<<<NH * SEQ, 32>>>();
    qout<<<SEQ, 64>>>(W2, b2, out);
}

// round 3
// speedup vs baseline: 1.5686x; 1.5686x over previous
#include <cuda_runtime.h>
#include <math.h>

#define NH 8
#define SEQ 32
#define DK 8
#define DM 64
#define PI_F 3.14159265358979323846f
#define W_MUL 0.6324555320336759f  // sqrt(2/5)

static __device__ float g_z[SEQ * NH * DK];   // [s][h*8+e]

__device__ __forceinline__ float2 cmul(float2 a, float2 b) {
    return make_float2(fmaf(a.x, b.x, -a.y * b.y), fmaf(a.x, b.y, a.y * b.x));
}
// a * conj(b)
__device__ __forceinline__ float2 cmulc(float2 a, float2 b) {
    return make_float2(fmaf(a.x, b.x, a.y * b.y), fmaf(a.y, b.x, -a.x * b.y));
}
__device__ __forceinline__ float2 cadd(float2 a, float2 b) {
    return make_float2(a.x + b.x, a.y + b.y);
}

// CNOT-ring basis permutation f(x)
__device__ __forceinline__ int permf(int x) {
#pragma unroll
    for (int t = 0; t < 6; t++) {
        int cb = 5 - t;
        int tb = 5 - ((t + 1) % 6);
        if ((x >> cb) & 1) x ^= (1 << tb);
    }
    return x;
}

__device__ __forceinline__ float2 bfly_sum8(float2 v) {
#pragma unroll
    for (int d = 1; d < 8; d <<= 1) {
        v.x += __shfl_xor_sync(0xffffffffu, v.x, d);
        v.y += __shfl_xor_sync(0xffffffffu, v.y, d);
    }
    return v;
}

// apply 3-qubit kron unitary (u[q][4], qubit 0 = MSB) to real vector psi[8]
__device__ __forceinline__ void apply_u3(const float2 (*u)[4], const float* psi,
                                         float2* v) {
#pragma unroll
    for (int e = 0; e < 8; e++) v[e] = make_float2(psi[e], 0.f);
#pragma unroll
    for (int q = 0; q < 3; q++) {
        int p = 2 - q;
        float2 u0 = u[q][0], u1 = u[q][1], u2 = u[q][2], u3 = u[q][3];
#pragma unroll
        for (int k = 0; k < 8; k++) {
            if ((k >> p) & 1) continue;
            int k1 = k | (1 << p);
            float2 v0 = v[k], v1 = v[k1];
            v[k]  = cadd(cmul(u0, v0), cmul(u1, v1));
            v[k1] = cadd(cmul(u2, v0), cmul(u3, v1));
        }
    }
}

// ---------------- Kernel 1: fused prep + scan ----------------
// grid = NH*16 blocks; block handles head h = bid>>4, chains i0 = (bid&15)*2, i0+1
__global__ void __launch_bounds__(64)
qmain(const float* __restrict__ x,     // (32,64)
      const float* __restrict__ pqc,   // (8,3,9)
      const float* __restrict__ W1,    // (8,64)
      const float* __restrict__ b1)    // (8,)
{
    const int h  = blockIdx.x >> 4;
    const int i0 = (blockIdx.x & 15) * 2;
    const int t  = threadIdx.x;      // 0..63
    const int w  = t >> 5;           // warp / chain index
    const int l  = t & 31;           // lane

    __shared__ float  s_x [SEQ][DM];       // 8KB staged x
    __shared__ float  s_W1[DK][DM];        // 2KB
    __shared__ float  s_xq [SEQ][DK];
    __shared__ float  s_psi[SEQ][DK];
    __shared__ float2 s_u[3][3][4];
    __shared__ float  s_qd[2][DK];
    __shared__ float  s_kd[SEQ][DK];
    __shared__ float  s_ms[64];
    __shared__ int    s_finv[64];
    __shared__ float  s_mk[SEQ][DK];
    __shared__ float2 s_phiv[SEQ][DK];
    __shared__ float2 s_uj[2][SEQ][4];
    __shared__ float2 s_chi[2][8];
    __shared__ float2 s_rho[2][2][64];

    // ---- Phase 0: tables + stage inputs (coalesced float4) ----
    {
        int y = permf(t);
        s_finv[y] = t;
        s_ms[t] = (__popc(y) & 1) ? -1.0f : 1.0f;
    }
    {
        const float4* xs = (const float4*)x;
        float4* xd = (float4*)&s_x[0][0];
#pragma unroll
        for (int k = 0; k < 8; k++) xd[t + 64 * k] = xs[t + 64 * k];
        const float4* ws = (const float4*)W1;
        float4* wd = (float4*)&s_W1[0][0];
#pragma unroll
        for (int k = 0; k < 2; k++) wd[t + 64 * k] = ws[t + 64 * k];
    }
    __syncthreads();

    // ---- Phase 1: xq = x @ W1^T + b1 (4 outputs/thread) ----
#pragma unroll
    for (int k = 0; k < 4; k++) {
        int idx = t + 64 * k;            // 0..255
        int s = idx >> 3, c = idx & 7;
        float acc = b1[c];
#pragma unroll 16
        for (int d = 0; d < DM; d++) acc = fmaf(s_x[s][d], s_W1[c][d], acc);
        s_xq[s][c] = acc;
    }
    __syncthreads();

    // ---- Phase 2: normalize; build 2x2 unitaries ----
#pragma unroll
    for (int k = 0; k < 4; k++) {
        int idx = t + 64 * k;
        int s = idx >> 3, c = idx & 7;
        float n = 0.f;
#pragma unroll
        for (int e = 0; e < DK; e++) n = fmaf(s_xq[s][e], s_xq[s][e], n);
        s_psi[s][c] = s_xq[s][c] * rsqrtf(n);
    }
    if (t < 9) {
        int g = t / 3, q = t % 3;
        const float* ap = pqc + h * 27 + g * 9 + q * 3;
        float a0 = ap[0] * W_MUL, a1 = ap[1] * W_MUL, a2 = ap[2] * W_MUL;
        float sx, cx, sy, cy, sz, cz;
        sincosf(0.5f * a0, &sx, &cx);
        sincosf(0.5f * a1, &sy, &cy);
        sincosf(0.5f * a2, &sz, &cz);
        float2 m00 = make_float2(cy * cx,   sy * sx);
        float2 m01 = make_float2(-sy * cx, -cy * sx);
        float2 m10 = make_float2(sy * cx,  -cy * sx);
        float2 m11 = make_float2(cy * cx,  -sy * sx);
        float2 e0 = make_float2(cz, -sz);
        float2 e1 = make_float2(cz,  sz);
        s_u[g][q][0] = cmul(e0, m00);
        s_u[g][q][1] = cmul(e0, m01);
        s_u[g][q][2] = cmul(e1, m10);
        s_u[g][q][3] = cmul(e1, m11);
    }
    __syncthreads();

    // ---- Phase 3: apply unitaries ----
    {
        float2 v[8];
        if (t < 32) {                     // kd for s = t
            apply_u3(s_u[1], s_psi[t], v);
#pragma unroll
            for (int e = 0; e < 8; e++)
                s_kd[t][e] = fmaf(v[e].x, v[e].x, v[e].y * v[e].y);
            if (t < 2) {                  // qd for chain t (s = i0 + t)
                float2 vq[8];
                apply_u3(s_u[0], s_psi[i0 + t], vq);
#pragma unroll
                for (int e = 0; e < 8; e++)
                    s_qd[t][e] = fmaf(vq[e].x, vq[e].x, vq[e].y * vq[e].y);
            }
        } else {                          // phiv for s = t-32
            int s = t - 32;
            apply_u3(s_u[2], s_psi[s], v);
#pragma unroll
            for (int e = 0; e < 8; e++) s_phiv[s][e] = v[e];
        }
    }
    __syncthreads();

    // ---- Phase 4: mk[j][c] = sum_d ms[8c+d] kd[j][d] ----
#pragma unroll
    for (int k = 0; k < 4; k++) {
        int idx = t + 64 * k;            // 0..255
        int j = idx >> 3, c = idx & 7;
        float acc = 0.f;
#pragma unroll
        for (int d = 0; d < 8; d++)
            acc = fmaf(s_ms[c * 8 + d], s_kd[j][d], acc);
        s_mk[j][c] = acc;
    }
    __syncthreads();

    // ---- Phase 5: phi rows + u(phi) per (chain, j) ----
    {
        int ci = w, j = l;
        float acc = 0.f;
#pragma unroll
        for (int c = 0; c < 8; c++) acc = fmaf(s_qd[ci][c], s_mk[j][c], acc);
        float ph = acc * PI_F;
        float s4, c4, sh, ch;
        sincosf(0.25f * ph, &s4, &c4);
        sincosf(0.50f * ph, &sh, &ch);
        float cc2 = c4 * c4, ss2 = s4 * s4, cs2 = c4 * s4;
        float2 e0 = make_float2(ch, -sh);
        float2 e1 = make_float2(ch,  sh);
        s_uj[ci][j][0] = cmul(e0, make_float2(cc2,  ss2));
        s_uj[ci][j][1] = cmul(e0, make_float2(-cs2, -cs2));
        s_uj[ci][j][2] = cmul(e1, make_float2(cs2,  -cs2));
        s_uj[ci][j][3] = cmul(e1, make_float2(cc2,  -ss2));
    }
    __syncthreads();

    // ---- Phase 6: warp-synchronous scan (warp w = chain i0+w) ----
    const int a0 = l >> 3;
    const int c  = l & 7;

    int ro0[8], ro1[8], co0[8], co1[8], coc[8];
#pragma unroll
    for (int b = 0; b < 8; b++) {
        int j0 = s_finv[a0 * 8 + b];
        int j1 = s_finv[(a0 + 4) * 8 + b];
        int jc = s_finv[c * 8 + b];
        ro0[b] = (j0 >> 3) * 8 + (jc >> 3);
        ro1[b] = (j1 >> 3) * 8 + (jc >> 3);
        co0[b] = j0 & 7;
        co1[b] = j1 & 7;
        coc[b] = jc & 7;
    }

    const int kf2a = (c >> 2) & 1;
    const int kf2b = 2 | ((c >> 2) & 1);
    const int kf1  = (((a0 >> 1) & 1) << 1) | ((c >> 1) & 1);
    const int kf0  = ((a0 & 1) << 1) | (c & 1);

    float2 acc0, acc1;
    int cur = 0;

    for (int j = 0; j < SEQ; j++) {
        const float2* uj = s_uj[w][j];
        float2 f20 = uj[kf2a], f21 = uj[kf2b];
        float2 f1  = uj[kf1],  f0  = uj[kf0];
        float2 pv  = s_phiv[j][c];

        float2 g  = cmul(f1, f0);
        float2 gp = cmul(g, pv);
        float2 t0 = cmul(f20, gp);
        float2 t1 = cmul(f21, gp);

        t0 = bfly_sum8(t0);   // chi[a0]
        t1 = bfly_sum8(t1);   // chi[a0+4]

        if ((l & 7) == 0) {
            s_chi[w][a0]     = t0;
            s_chi[w][a0 + 4] = t1;
        }
        __syncwarp();

        if (j == 0) {
            acc0 = cmulc(s_chi[w][a0],     s_chi[w][c]);
            acc1 = cmulc(s_chi[w][a0 + 4], s_chi[w][c]);
        } else {
            const float2* rp = s_rho[w][cur];
            acc0 = make_float2(0.f, 0.f);
            acc1 = make_float2(0.f, 0.f);
#pragma unroll
            for (int b = 0; b < 8; b++) {
                float2 cq = s_chi[w][coc[b]];
                float2 c0 = s_chi[w][co0[b]];
                float2 c1 = s_chi[w][co1[b]];
                float2 w0 = cmulc(c0, cq);
                float2 w1 = cmulc(c1, cq);
                float2 r0 = rp[ro0[b]];
                float2 r1 = rp[ro1[b]];
                acc0 = cadd(acc0, cmul(r0, w0));
                acc1 = cadd(acc1, cmul(r1, w1));
            }
        }
        s_rho[w][cur ^ 1][l]      = acc0;
        s_rho[w][cur ^ 1][l + 32] = acc1;
        cur ^= 1;
        __syncwarp();
    }

    if (l < 8) {
        float2 v = s_rho[w][cur][l * 9];    // diagonal (l,l)
        int i = i0 + w;
        g_z[i * (NH * DK) + h * DK + l] = v.x;
    }
}

// ---------------- Kernel 2: output projection ----------------
__global__ void __launch_bounds__(64)
qout(const float* __restrict__ W2,   // (64,64)
     const float* __restrict__ b2,   // (64,)
     float* __restrict__ out)        // (1,32,64)
{
    const int s = blockIdx.x;   // 0..31
    const int t = threadIdx.x;  // 0..63

    __shared__ float sW[DM * 65];
    __shared__ float sz[DM];

    sz[t] = g_z[s * DM + t];
    {
        const float4* ws = (const float4*)W2;
#pragma unroll
        for (int k = 0; k < 16; k++) {
            int q = t + 64 * k;              // float4 index, coalesced
            float4 v = ws[q];
            int base = q * 4;
            int row = base >> 6, col = base & 63;
            float* dst = &sW[row * 65 + col];
            dst[0] = v.x; dst[1] = v.y; dst[2] = v.z; dst[3] = v.w;
        }
    }
    __syncthreads();

    float acc = b2[t];
#pragma unroll
    for (int e = 0; e < DM; e++)
        acc = fmaf(sz[e], sW[t * 65 + e], acc);
    out[s * DM + t] = acc;
}

extern "C" void kernel_launch(void* const* d_in, const int* in_sizes, int n_in,
                              void* d_out, int out_size) {
    const float* x    = (const float*)d_in[0];
    const float* pqc  = (const float*)d_in[1];
    const float* W1   = (const float*)d_in[2];
    const float* b1   = (const float*)d_in[3];
    const float* W2   = (const float*)d_in[4];
    const float* b2   = (const float*)d_in[5];
    float* out = (float*)d_out;

    qmain<<<NH * 16, 64>>>(x, pqc, W1, b1);
    qout<<<SEQ, 64>>>(W2, b2, out);
}

// round 4
// speedup vs baseline: 1.9439x; 1.2393x over previous
#include <cuda_runtime.h>
#include <math.h>

#define NH 8
#define SEQ 32
#define DK 8
#define DM 64
#define PI_F 3.14159265358979323846f
#define W_MUL 0.6324555320336759f  // sqrt(2/5)

static __device__ float g_z[SEQ * NH * DK];   // [s][h*8+e]

__device__ __forceinline__ float2 cmul(float2 a, float2 b) {
    return make_float2(fmaf(a.x, b.x, -a.y * b.y), fmaf(a.x, b.y, a.y * b.x));
}
// a * conj(b)
__device__ __forceinline__ float2 cmulc(float2 a, float2 b) {
    return make_float2(fmaf(a.x, b.x, a.y * b.y), fmaf(a.y, b.x, -a.x * b.y));
}
__device__ __forceinline__ float2 cadd(float2 a, float2 b) {
    return make_float2(a.x + b.x, a.y + b.y);
}
// acc += a * b (complex)
__device__ __forceinline__ void cmac(float2& acc, float2 a, float2 b) {
    acc.x = fmaf(a.x, b.x, fmaf(-a.y, b.y, acc.x));
    acc.y = fmaf(a.x, b.y, fmaf( a.y, b.x, acc.y));
}

// CNOT-ring basis permutation f(x)
__device__ __forceinline__ int permf(int x) {
#pragma unroll
    for (int t = 0; t < 6; t++) {
        int cb = 5 - t;
        int tb = 5 - ((t + 1) % 6);
        if ((x >> cb) & 1) x ^= (1 << tb);
    }
    return x;
}

// apply 3-qubit kron unitary (u[q][4], qubit 0 = MSB) to real vector psi[8]
__device__ __forceinline__ void apply_u3(const float2 (*u)[4], const float* psi,
                                         float2* v) {
#pragma unroll
    for (int e = 0; e < 8; e++) v[e] = make_float2(psi[e], 0.f);
#pragma unroll
    for (int q = 0; q < 3; q++) {
        int p = 2 - q;
        float2 u0 = u[q][0], u1 = u[q][1], u2 = u[q][2], u3 = u[q][3];
#pragma unroll
        for (int k = 0; k < 8; k++) {
            if ((k >> p) & 1) continue;
            int k1 = k | (1 << p);
            float2 v0 = v[k], v1 = v[k1];
            v[k]  = cadd(cmul(u0, v0), cmul(u1, v1));
            v[k1] = cadd(cmul(u2, v0), cmul(u3, v1));
        }
    }
}

#define WPAD 65   // padded row (float2) for W table

// ---------------- Kernel 1: fused prep + scan ----------------
// grid = NH*16; block: head h = bid>>4, chains i0 = (bid&15)*2 + {0,1}
__global__ void __launch_bounds__(64)
qmain(const float* __restrict__ x,     // (32,64)
      const float* __restrict__ pqc,   // (8,3,9)
      const float* __restrict__ W1,    // (8,64)
      const float* __restrict__ b1)    // (8,)
{
    const int h  = blockIdx.x >> 4;
    const int i0 = (blockIdx.x & 15) * 2;
    const int t  = threadIdx.x;      // 0..63
    const int w  = t >> 5;           // warp / chain index
    const int l  = t & 31;           // lane

    // W-table aliases the x/W1 staging area (dead after Phase 1)
    __shared__ union {
        struct { float x[SEQ][DM]; float W1[DK][DM]; } pre;  // 10 KB
        float2 W[2][SEQ][WPAD];                              // 33.3 KB
    } ub;
    __shared__ float  s_xq [SEQ][DK];
    __shared__ float  s_psi[SEQ][DK];
    __shared__ float2 s_u[3][3][4];
    __shared__ float  s_qd[2][DK];
    __shared__ float  s_kd[SEQ][DK];
    __shared__ float  s_ms[64];
    __shared__ int    s_finv[64];
    __shared__ float  s_mkT[DK][SEQ];      // transposed mk
    __shared__ float2 s_phivT[DK][SEQ];    // transposed phiv
    __shared__ float2 s_rho[2][2][64];     // [warp][buf][64]

    // ---- Phase 0: tables + stage inputs ----
    {
        int y = permf(t);
        s_finv[y] = t;
        s_ms[t] = (__popc(y) & 1) ? -1.0f : 1.0f;
    }
    {
        const float4* xs = (const float4*)x;
        float4* xd = (float4*)&ub.pre.x[0][0];
#pragma unroll
        for (int k = 0; k < 8; k++) xd[t + 64 * k] = xs[t + 64 * k];
        const float4* ws = (const float4*)W1;
        float4* wd = (float4*)&ub.pre.W1[0][0];
#pragma unroll
        for (int k = 0; k < 2; k++) wd[t + 64 * k] = ws[t + 64 * k];
    }
    __syncthreads();

    // ---- Phase 1: xq = x @ W1^T + b1 ----
#pragma unroll
    for (int k = 0; k < 4; k++) {
        int idx = t + 64 * k;            // 0..255
        int s = idx >> 3, c = idx & 7;
        float acc = b1[c];
#pragma unroll 16
        for (int d = 0; d < DM; d++) acc = fmaf(ub.pre.x[s][d], ub.pre.W1[c][d], acc);
        s_xq[s][c] = acc;
    }
    __syncthreads();

    // ---- Phase 2: normalize; build per-qubit 2x2 unitaries ----
#pragma unroll
    for (int k = 0; k < 4; k++) {
        int idx = t + 64 * k;
        int s = idx >> 3, c = idx & 7;
        float n = 0.f;
#pragma unroll
        for (int e = 0; e < DK; e++) n = fmaf(s_xq[s][e], s_xq[s][e], n);
        s_psi[s][c] = s_xq[s][c] * rsqrtf(n);
    }
    if (t < 9) {
        int g = t / 3, q = t % 3;
        const float* ap = pqc + h * 27 + g * 9 + q * 3;
        float a0 = ap[0] * W_MUL, a1 = ap[1] * W_MUL, a2 = ap[2] * W_MUL;
        float sx, cx, sy, cy, sz, cz;
        sincosf(0.5f * a0, &sx, &cx);
        sincosf(0.5f * a1, &sy, &cy);
        sincosf(0.5f * a2, &sz, &cz);
        float2 m00 = make_float2(cy * cx,   sy * sx);
        float2 m01 = make_float2(-sy * cx, -cy * sx);
        float2 m10 = make_float2(sy * cx,  -cy * sx);
        float2 m11 = make_float2(cy * cx,  -sy * sx);
        float2 e0 = make_float2(cz, -sz);
        float2 e1 = make_float2(cz,  sz);
        s_u[g][q][0] = cmul(e0, m00);
        s_u[g][q][1] = cmul(e0, m01);
        s_u[g][q][2] = cmul(e1, m10);
        s_u[g][q][3] = cmul(e1, m11);
    }
    __syncthreads();

    // ---- Phase 3: apply head unitaries ----
    {
        float2 v[8];
        if (t < 32) {                     // kd for s = t
            apply_u3(s_u[1], s_psi[t], v);
#pragma unroll
            for (int e = 0; e < 8; e++)
                s_kd[t][e] = fmaf(v[e].x, v[e].x, v[e].y * v[e].y);
            if (t < 2) {                  // qd for chain t
                float2 vq[8];
                apply_u3(s_u[0], s_psi[i0 + t], vq);
#pragma unroll
                for (int e = 0; e < 8; e++)
                    s_qd[t][e] = fmaf(vq[e].x, vq[e].x, vq[e].y * vq[e].y);
            }
        } else {                          // phiv (transposed) for s = t-32
            int s = t - 32;
            apply_u3(s_u[2], s_psi[s], v);
#pragma unroll
            for (int e = 0; e < 8; e++) s_phivT[e][s] = v[e];
        }
    }
    __syncthreads();

    // ---- Phase 4: mkT[c][j] = sum_d ms[8c+d] kd[j][d] ----
#pragma unroll
    for (int k = 0; k < 4; k++) {
        int idx = t + 64 * k;            // 0..255
        int j = idx >> 3, c = idx & 7;
        float acc = 0.f;
#pragma unroll
        for (int d = 0; d < 8; d++)
            acc = fmaf(s_ms[c * 8 + d], s_kd[j][d], acc);
        s_mkT[c][j] = acc;
    }
    __syncthreads();

    // ---- Phase 5: per (chain=w, j=l): chi_j = Uw(phi_j) phiv_j; W table ----
    {
        float acc = 0.f;
#pragma unroll
        for (int c = 0; c < 8; c++) acc = fmaf(s_qd[w][c], s_mkT[c][l], acc);
        float ph = acc * PI_F;
        float s4, c4, sh, ch;
        sincosf(0.25f * ph, &s4, &c4);
        sincosf(0.50f * ph, &sh, &ch);
        float cc2 = c4 * c4, ss2 = s4 * s4, cs2 = c4 * s4;
        float2 e0 = make_float2(ch, -sh);
        float2 e1 = make_float2(ch,  sh);
        float2 uu[1][4];
        uu[0][0] = cmul(e0, make_float2(cc2,  ss2));
        uu[0][1] = cmul(e0, make_float2(-cs2, -cs2));
        uu[0][2] = cmul(e1, make_float2(cs2,  -cs2));
        uu[0][3] = cmul(e1, make_float2(cc2,  -ss2));

        // chi = kron(u,u,u) * phiv_l  (3-stage butterfly, same u each qubit)
        float2 v[8];
#pragma unroll
        for (int e = 0; e < 8; e++) v[e] = s_phivT[e][l];
#pragma unroll
        for (int q = 0; q < 3; q++) {
            int p = 2 - q;
            float2 u0 = uu[0][0], u1 = uu[0][1], u2 = uu[0][2], u3 = uu[0][3];
#pragma unroll
            for (int k = 0; k < 8; k++) {
                if ((k >> p) & 1) continue;
                int k1 = k | (1 << p);
                float2 v0 = v[k], v1 = v[k1];
                v[k]  = cadd(cmul(u0, v0), cmul(u1, v1));
                v[k1] = cadd(cmul(u2, v0), cmul(u3, v1));
            }
        }
        // W_j[y1*8+y2] = chi[y1] * conj(chi[y2])
        float2* wrow = &ub.W[w][l][0];
#pragma unroll
        for (int y1 = 0; y1 < 8; y1++)
#pragma unroll
            for (int y2 = 0; y2 < 8; y2++)
                wrow[y1 * 8 + y2] = cmulc(v[y1], v[y2]);
    }

    // ---- Phase 6: gather tables (per-lane constants) ----
    const int a0 = l >> 3;
    const int c  = l & 7;
    int ro0[8], ro1[8], y0[8], y1[8];
#pragma unroll
    for (int b = 0; b < 8; b++) {
        int p0 = s_finv[a0 * 8 + b];
        int p1 = s_finv[(a0 + 4) * 8 + b];
        int pc = s_finv[c * 8 + b];
        ro0[b] = (p0 >> 3) * 8 + (pc >> 3);
        ro1[b] = (p1 >> 3) * 8 + (pc >> 3);
        y0[b]  = (p0 & 7) * 8 + (pc & 7);
        y1[b]  = (p1 & 7) * 8 + (pc & 7);
    }
    __syncwarp();   // W table (warp-local) ready

    // ---- Phase 7: scan; rho_0 = W_0 outer row ----
    s_rho[w][0][l]      = ub.W[w][0][l];
    s_rho[w][0][l + 32] = ub.W[w][0][l + 32];
    int cur = 0;
    __syncwarp();

    for (int j = 1; j < SEQ; j++) {
        const float2* rp = s_rho[w][cur];
        const float2* wj = &ub.W[w][j][0];
        float2 acc0 = make_float2(0.f, 0.f);
        float2 acc1 = make_float2(0.f, 0.f);
#pragma unroll
        for (int b = 0; b < 8; b++) {
            cmac(acc0, rp[ro0[b]], wj[y0[b]]);
            cmac(acc1, rp[ro1[b]], wj[y1[b]]);
        }
        s_rho[w][cur ^ 1][l]      = acc0;
        s_rho[w][cur ^ 1][l + 32] = acc1;
        cur ^= 1;
        __syncwarp();
    }

    if (l < 8) {
        float2 v = s_rho[w][cur][l * 9];    // diagonal (l,l)
        int i = i0 + w;
        g_z[i * (NH * DK) + h * DK + l] = v.x;
    }
}

// ---------------- Kernel 2: output projection ----------------
// grid = 8, block = 256: block handles 4 sequences
__global__ void __launch_bounds__(256)
qout(const float* __restrict__ W2,   // (64,64)
     const float* __restrict__ b2,   // (64,)
     float* __restrict__ out)        // (1,32,64)
{
    const int t = threadIdx.x;          // 0..255
    const int sblk = blockIdx.x * 4;

    __shared__ float sW[DM * 65];
    __shared__ float sz[4][DM];

    {
        const float4* ws = (const float4*)W2;
#pragma unroll
        for (int k = 0; k < 4; k++) {
            int q = t + 256 * k;             // float4 idx, coalesced
            float4 v = ws[q];
            int base = q * 4;
            int row = base >> 6, col = base & 63;
            float* dst = &sW[row * 65 + col];
            dst[0] = v.x; dst[1] = v.y; dst[2] = v.z; dst[3] = v.w;
        }
    }
    sz[t >> 6][t & 63] = g_z[sblk * DM + t];
    __syncthreads();

    const int s = t >> 6;    // 0..3
    const int d = t & 63;
    float acc = b2[d];
#pragma unroll
    for (int e = 0; e < DM; e++)
        acc = fmaf(sz[s][e], sW[d * 65 + e], acc);
    out[(sblk + s) * DM + d] = acc;
}

extern "C" void kernel_launch(void* const* d_in, const int* in_sizes, int n_in,
                              void* d_out, int out_size) {
    const float* x    = (const float*)d_in[0];
    const float* pqc  = (const float*)d_in[1];
    const float* W1   = (const float*)d_in[2];
    const float* b1   = (const float*)d_in[3];
    const float* W2   = (const float*)d_in[4];
    const float* b2   = (const float*)d_in[5];
    float* out = (float*)d_out;

    qmain<<<NH * 16, 64>>>(x, pqc, W1, b1);
    qout<<<8, 256>>>(W2, b2, out);
}